// round 10
// baseline (speedup 1.0000x reference)
#include <cuda_runtime.h>
#include <cstdint>

// TMA-bulk streaming reduction over three fp32 arrays, globally balanced,
// with a fixed-point atomic epilogue.
// R1-R9 verdict: path-independent chip throughput cap (~5.85 TB/s here);
// transfer floor ~38.6us. This round removes post-transfer serial work:
// each block adds its partial as 2^40-scaled int64 via atomicAdd (integer
// adds commute -> bitwise deterministic), last finisher converts & writes.

#define NT 256
#define NBLK 296                         // 148 SMs x 2
#define STAGES 4
#define TILE4 1024                       // float4 per tile = 16KB
#define TILE_BYTES (TILE4 * 16)
#define SMEM_BYTES (STAGES * TILE_BYTES + STAGES * 8)

#define FX_SCALE 1099511627776.0         // 2^40

__device__ unsigned long long g_sum = 0ull;
__device__ unsigned int g_count = 0;

__device__ __forceinline__ uint32_t smem_u32(const void* p) {
    uint32_t a;
    asm("{ .reg .u64 t; cvta.to.shared.u64 t, %1; cvt.u32.u64 %0, t; }"
        : "=r"(a) : "l"(p));
    return a;
}

__device__ __forceinline__ void mbar_init(uint32_t bar, uint32_t cnt) {
    asm volatile("mbarrier.init.shared.b64 [%0], %1;" :: "r"(bar), "r"(cnt) : "memory");
}

__device__ __forceinline__ void mbar_expect_tx(uint32_t bar, uint32_t bytes) {
    asm volatile("mbarrier.arrive.expect_tx.shared.b64 _, [%0], %1;"
                 :: "r"(bar), "r"(bytes) : "memory");
}

__device__ __forceinline__ void bulk_g2s(uint32_t dst, const void* src,
                                         uint32_t bytes, uint32_t bar) {
    asm volatile(
        "cp.async.bulk.shared::cta.global.mbarrier::complete_tx::bytes "
        "[%0], [%1], %2, [%3];"
        :: "r"(dst), "l"(src), "r"(bytes), "r"(bar) : "memory");
}

__device__ __forceinline__ void mbar_wait(uint32_t bar, uint32_t parity) {
    uint32_t done;
    asm volatile(
        "{\n\t.reg .pred p;\n\t"
        "mbarrier.try_wait.parity.acquire.cta.shared::cta.b64 p, [%1], %2;\n\t"
        "selp.b32 %0, 1, 0, p;\n\t}"
        : "=r"(done) : "r"(bar), "r"(parity) : "memory");
    if (!done) {
        asm volatile(
            "{\n\t.reg .pred P1;\n\t"
            "W_%=:\n\t"
            "mbarrier.try_wait.parity.acquire.cta.shared::cta.b64 P1, [%0], %1, 0x989680;\n\t"
            "@P1 bra.uni D_%=;\n\t"
            "bra.uni W_%=;\n\t"
            "D_%=:\n\t}"
            :: "r"(bar), "r"(parity) : "memory");
    }
}

__device__ __forceinline__ float warp_reduce(float v) {
    #pragma unroll
    for (int off = 16; off > 0; off >>= 1)
        v += __shfl_down_sync(0xFFFFFFFFu, v, off);
    return v;
}

// Map global tile index -> (source pointer, tile length in float4).
struct TileSrc { const float4* p; int len; };

__device__ __forceinline__ TileSrc tile_map(
    int t,
    const float4* a, int ta, int na4,
    const float4* b, int tb, int nb4,
    const float4* c, int nc4)
{
    TileSrc r;
    if (t < ta) {
        const int off = t * TILE4;
        r.p = a + off;
        r.len = (na4 - off >= TILE4) ? TILE4 : (na4 - off);
    } else if (t < ta + tb) {
        const int off = (t - ta) * TILE4;
        r.p = b + off;
        r.len = (nb4 - off >= TILE4) ? TILE4 : (nb4 - off);
    } else {
        const int off = (t - ta - tb) * TILE4;
        r.p = c + off;
        r.len = (nc4 - off >= TILE4) ? TILE4 : (nc4 - off);
    }
    return r;
}

__global__ __launch_bounds__(NT, 2) void sum3_tma_fx(
    const float4* __restrict__ a, int na4,
    const float4* __restrict__ b, int nb4,
    const float4* __restrict__ c, int nc4,
    float* __restrict__ out)
{
    extern __shared__ __align__(128) unsigned char smem[];
    const float4* __restrict__ buf = (const float4*)smem;
    const uint32_t smem_base = smem_u32(smem);
    const uint32_t bar_base  = smem_base + STAGES * TILE_BYTES;

    const int ta = (na4 + TILE4 - 1) / TILE4;
    const int tb = (nb4 + TILE4 - 1) / TILE4;
    const int tc = (nc4 + TILE4 - 1) / TILE4;
    const int T  = ta + tb + tc;

    // Consecutive tile range for this block: floor/ceil balanced.
    const int q = T / NBLK, r = T % NBLK;
    const int cnt   = q + (blockIdx.x < (unsigned)r ? 1 : 0);
    const int start = blockIdx.x * q + min((int)blockIdx.x, r);

    if (threadIdx.x == 0) {
        #pragma unroll
        for (int s = 0; s < STAGES; s++) mbar_init(bar_base + 8u * s, 1);
    }
    __syncthreads();

    // Prologue: fill the pipeline.
    if (threadIdx.x == 0) {
        const int pre = (cnt < STAGES) ? cnt : STAGES;
        for (int i = 0; i < pre; i++) {
            TileSrc ts = tile_map(start + i, a, ta, na4, b, tb, nb4, c, nc4);
            const uint32_t bytes = (uint32_t)ts.len * 16u;
            mbar_expect_tx(bar_base + 8u * i, bytes);
            bulk_g2s(smem_base + (uint32_t)i * TILE_BYTES, ts.p, bytes,
                     bar_base + 8u * i);
        }
    }

    float s0 = 0.f, s1 = 0.f, s2 = 0.f, s3 = 0.f;
    const int tx = threadIdx.x;

    for (int i = 0; i < cnt; i++) {
        const int s  = i & (STAGES - 1);
        const uint32_t ph = (uint32_t)(i / STAGES) & 1u;
        mbar_wait(bar_base + 8u * s, ph);

        TileSrc ts = tile_map(start + i, a, ta, na4, b, tb, nb4, c, nc4);
        const float4* __restrict__ tbuf = buf + s * TILE4;

        if (ts.len == TILE4) {
            float4 v0 = tbuf[tx];
            float4 v1 = tbuf[tx + NT];
            float4 v2 = tbuf[tx + 2 * NT];
            float4 v3 = tbuf[tx + 3 * NT];
            s0 += (v0.x + v0.y) + (v0.z + v0.w);
            s1 += (v1.x + v1.y) + (v1.z + v1.w);
            s2 += (v2.x + v2.y) + (v2.z + v2.w);
            s3 += (v3.x + v3.y) + (v3.z + v3.w);
        } else {
            #pragma unroll
            for (int k = 0; k < 4; k++) {
                const int j = tx + k * NT;
                if (j < ts.len) {
                    float4 v = tbuf[j];
                    s0 += (v.x + v.y) + (v.z + v.w);
                }
            }
        }
        __syncthreads();   // slot s fully consumed by all threads

        if (threadIdx.x == 0 && i + STAGES < cnt) {
            TileSrc t2 = tile_map(start + i + STAGES, a, ta, na4, b, tb, nb4, c, nc4);
            const uint32_t bytes = (uint32_t)t2.len * 16u;
            mbar_expect_tx(bar_base + 8u * s, bytes);
            bulk_g2s(smem_base + (uint32_t)s * TILE_BYTES, t2.p, bytes,
                     bar_base + 8u * s);
        }
    }

    float s = (s0 + s1) + (s2 + s3);

    // Block reduce.
    __shared__ float sh[NT / 32];
    s = warp_reduce(s);
    const int lane = threadIdx.x & 31;
    const int wid  = threadIdx.x >> 5;
    if (lane == 0) sh[wid] = s;
    __syncthreads();

    if (threadIdx.x == 0) {
        float v = 0.f;
        #pragma unroll
        for (int k = 0; k < NT / 32; k++) v += sh[k];

        // Fixed-point atomic accumulate: integer adds commute -> bitwise
        // deterministic result independent of block arrival order.
        long long fx = (long long)((double)v * FX_SCALE);
        atomicAdd(&g_sum, (unsigned long long)fx);
        __threadfence();
        unsigned int done = atomicAdd(&g_count, 1u);
        if (done == (unsigned)(NBLK - 1)) {
            // All sum-adds are fenced-before their count-adds -> visible here.
            unsigned long long acc = atomicAdd(&g_sum, 0ull);   // atomic read at L2
            out[0] = (float)((double)(long long)acc * (1.0 / FX_SCALE));
            g_sum = 0ull;          // reset for next graph replay
            g_count = 0u;
        }
    }
}

extern "C" void kernel_launch(void* const* d_in, const int* in_sizes, int n_in,
                              void* d_out, int out_size)
{
    const float4* a = (const float4*)d_in[0];
    const float4* b = (const float4*)d_in[1];
    const float4* c = (const float4*)d_in[2];
    const int na4 = in_sizes[0] / 4;
    const int nb4 = in_sizes[1] / 4;
    const int nc4 = in_sizes[2] / 4;

    cudaFuncSetAttribute(sum3_tma_fx, cudaFuncAttributeMaxDynamicSharedMemorySize,
                         SMEM_BYTES);
    sum3_tma_fx<<<NBLK, NT, SMEM_BYTES>>>(a, na4, b, nb4, c, nc4, (float*)d_out);
}